// round 8
// baseline (speedup 1.0000x reference)
#include <cuda_runtime.h>
#include <cuda_fp16.h>
#include <math.h>
#include <stdint.h>

#define MTOT 16384

// ---------------- scratch ----------------
__device__ __align__(1024) __half g_xall[(size_t)MTOT * 512];
__device__ float  g_q   [(size_t)MTOT * 256];
__device__ float  g_kv  [(size_t)MTOT * 512];
__device__ float  g_h1  [(size_t)MTOT * 256];
__device__ float  g_offs[(size_t)MTOT * 18];
__device__ __align__(1024) __half g_att [(size_t)MTOT * 256];
__device__ float  g_xres[(size_t)MTOT * 256];
__device__ __align__(1024) __half g_xn2 [(size_t)MTOT * 256];
__device__ __align__(1024) __half g_hid [(size_t)MTOT * 1024];
__device__ __align__(1024) __half g_wr  [256 * 4608];
__device__ __align__(1024) __half g_wh  [65536 + 131072 + 65536 + 262144 + 262144];
__device__ float2 g_part[256];
__device__ float  g_st1 [16];
__device__ float  g_st2 [8];

// ---------------- fused weight prep: conv repack + 5x f2h ----------------
// ranges: [0,1179648) repack | q 65536 | kv 131072 | proj 65536 | fc1 262144 | fc2 262144
__global__ void prep_k(const float* __restrict__ off1_w, __half* __restrict__ wr,
                       const float* __restrict__ q_w,    __half* __restrict__ qwh,
                       const float* __restrict__ kv_w,   __half* __restrict__ kvwh,
                       const float* __restrict__ proj_w, __half* __restrict__ pwh,
                       const float* __restrict__ fc1_w,  __half* __restrict__ f1wh,
                       const float* __restrict__ fc2_w,  __half* __restrict__ f2wh) {
    int id = blockIdx.x * 256 + threadIdx.x;
    if (id < 1179648) {
        int o = id / 4608, k = id - o * 4608;
        int nb = k >> 9, c = k & 511;
        int ky = nb / 3, kx = nb - ky * 3;
        wr[id] = __float2half(off1_w[((size_t)o * 512 + c) * 9 + ky * 3 + kx]);
        return;
    }
    id -= 1179648;
    if (id < 65536)  { qwh [id] = __float2half(q_w [id]); return; }  id -= 65536;
    if (id < 131072) { kvwh[id] = __float2half(kv_w[id]); return; }  id -= 131072;
    if (id < 65536)  { pwh [id] = __float2half(proj_w[id]); return; } id -= 65536;
    if (id < 262144) { f1wh[id] = __float2half(fc1_w[id]); return; }  id -= 262144;
    f2wh[id] = __float2half(fc2_w[id]);
}

// ---------------- groupnorm stats: phase 1 ----------------
__global__ void gn_p1(const float* __restrict__ A, const float* __restrict__ B2,
                      float2* __restrict__ part) {
    int bi = blockIdx.x;
    int slab = bi >> 5, chunk = bi & 31;
    int tensor = slab >> 2, batch = slab & 3;
    const float* src = (tensor ? B2 : A) + ((size_t)batch << 20) + ((size_t)chunk << 15);
    const float4* p4 = reinterpret_cast<const float4*>(src);
    float s = 0.f, s2 = 0.f;
    for (int i = threadIdx.x; i < 8192; i += 256) {
        float4 v = p4[i];
        s  += v.x + v.y + v.z + v.w;
        s2 += v.x * v.x + v.y * v.y + v.z * v.z + v.w * v.w;
    }
    __shared__ float sh1[256], sh2[256];
    sh1[threadIdx.x] = s; sh2[threadIdx.x] = s2;
    __syncthreads();
    for (int st = 128; st > 0; st >>= 1) {
        if (threadIdx.x < st) { sh1[threadIdx.x] += sh1[threadIdx.x + st];
                                sh2[threadIdx.x] += sh2[threadIdx.x + st]; }
        __syncthreads();
    }
    if (threadIdx.x == 0) part[slab * 32 + chunk] = make_float2(sh1[0], sh2[0]);
}

// ---------------- groupnorm stats: phase 2 ----------------
__global__ void gn_p2(const float2* __restrict__ part, float* __restrict__ stats, int nslab) {
    int slab = threadIdx.x >> 5, lane = threadIdx.x & 31;
    if (slab >= nslab) return;
    float2 v = part[slab * 32 + lane];
    float s = v.x, s2 = v.y;
#pragma unroll
    for (int off = 16; off > 0; off >>= 1) {
        s  += __shfl_xor_sync(0xffffffffu, s,  off);
        s2 += __shfl_xor_sync(0xffffffffu, s2, off);
    }
    if (lane == 0) {
        float inv = 1.f / 1048576.f;
        float mu = s * inv;
        float var = s2 * inv - mu * mu;
        stats[slab * 2] = mu;
        stats[slab * 2 + 1] = rsqrtf(var + 1e-5f);
    }
}

// ---------------- normalize + NCHW->NHWC pack (fp16 out) ----------------
__global__ void norm_pack_k(const float* __restrict__ xq, const float* __restrict__ xkv,
                            const float* __restrict__ stats, const float* __restrict__ w,
                            const float* __restrict__ bb, __half* __restrict__ xall) {
    __shared__ float tile[32][33];
    int bz = blockIdx.z;
    int tensor = bz >> 2, batch = bz & 3;
    const float* src = (tensor == 0 ? xq : xkv) + ((size_t)batch << 20);
    float mu = stats[bz * 2], rstd = stats[bz * 2 + 1];
    int s0 = blockIdx.x * 32, c0 = blockIdx.y * 32;
    int tx = threadIdx.x, ty = threadIdx.y;
#pragma unroll
    for (int k = 0; k < 4; k++) {
        int c = c0 + ty + k * 8;
        tile[ty + k * 8][tx] = src[(size_t)c * 4096 + s0 + tx];
    }
    __syncthreads();
#pragma unroll
    for (int k = 0; k < 4; k++) {
        int sl = ty + k * 8;
        int c = c0 + tx;
        float v = (tile[tx][sl] - mu) * rstd * w[c] + bb[c];
        xall[(((size_t)batch * 4096 + s0 + sl) << 9) + tensor * 256 + c] = __float2half(v);
    }
}

// ---------------- norm2 (fp16 out) ----------------
__global__ void norm2_k(const float* __restrict__ xres, const float* __restrict__ stats,
                        const float* __restrict__ w, const float* __restrict__ bb,
                        __half* __restrict__ xn) {
    int id = blockIdx.x * blockDim.x + threadIdx.x;
    if (id >= MTOT * 256) return;
    int b = id >> 20, c = id & 255;
    xn[id] = __float2half((xres[id] - stats[b * 2]) * stats[b * 2 + 1] * w[c] + bb[c]);
}

// ---------------- PTX helpers ----------------
__device__ __forceinline__ void mma16(float4& d, const uint32_t* a, const uint32_t* b) {
    asm volatile("mma.sync.aligned.m16n8k16.row.col.f32.f16.f16.f32 "
        "{%0,%1,%2,%3}, {%4,%5,%6,%7}, {%8,%9}, {%0,%1,%2,%3};\n"
        : "+f"(d.x), "+f"(d.y), "+f"(d.z), "+f"(d.w)
        : "r"(a[0]), "r"(a[1]), "r"(a[2]), "r"(a[3]), "r"(b[0]), "r"(b[1]));
}
__device__ __forceinline__ void ldsm4(uint32_t* r, uint32_t a) {
    asm volatile("ldmatrix.sync.aligned.m8n8.x4.shared.b16 {%0,%1,%2,%3}, [%4];"
        : "=r"(r[0]), "=r"(r[1]), "=r"(r[2]), "=r"(r[3]) : "r"(a));
}
__device__ __forceinline__ void cp16(uint32_t d, const void* s, int sz) {
    asm volatile("cp.async.cg.shared.global [%0], [%1], 16, %2;"
        :: "r"(d), "l"(s), "r"(sz));
}
#define CP_COMMIT() asm volatile("cp.async.commit_group;")

// ---------------- multi-job fp16 tensor-core GEMM ----------------
// C[M,N] = A[M,K] @ W[N,K]^T + bias (A, W fp16; accum/bias fp32). M = 16384.
// mode 0 plain / 1 *scale / 2 relu / 3 gelu->HALF out / 4 +R(NCHW)->NHWC / 5 +R(NHWC)->NCHW
// CTA tile 256x128x64(halves), 256 thr (8 warps 4Mx2N, warp 64x64), 2-stage cp.async.
// Stage: A 256x128B (32KB) + B 128x128B (16KB) = 48KB. 8 chunks/row, swz c^(row&7).
#define STG_BYTES 49152
#define SMEM_REQ  (2 * STG_BYTES)
#define B_OFF     32768

struct GJob {
    const __half* A; const __half* W; const float* bias; float* C; const float* R;
    int N, K, lda, mode, im2col; float scale;
};

__device__ __forceinline__ void issue_tile(
    uint32_t sa0, const __half* __restrict__ A, const __half* __restrict__ W,
    int bm, int bn, int K0, int lda, int K, int im2col, int tid)
{
    // A: 256 rows x 8 chunks = 2048
#pragma unroll
    for (int i = 0; i < 8; i++) {
        const int idx = tid + (i << 8);
        const int row = idx >> 3, c = idx & 7;
        const __half* srcA; int szA = 16;
        if (!im2col) {
            srcA = A + (size_t)(bm + row) * lda + K0 + c * 8;
        } else {
            const int gm = bm + row;
            const int ib = gm >> 12, sp = gm & 4095;
            const int iy = sp >> 6, ix = sp & 63;
            const int nb = K0 >> 9, cc0 = K0 & 511;
            const int qy = nb / 3;
            const int yy = iy + qy - 1, xx = ix + (nb - qy * 3) - 1;
            srcA = A + (((size_t)(ib << 12) + (yy << 6) + xx) << 9) + cc0 + c * 8;
            if (!(yy >= 0 && yy < 64 && xx >= 0 && xx < 64)) { szA = 0; srcA = A; }
        }
        cp16(sa0 + row * 128 + ((c ^ (row & 7)) << 4), srcA, szA);
    }
    // B: 128 rows x 8 chunks = 1024
#pragma unroll
    for (int i = 0; i < 4; i++) {
        const int idx = tid + (i << 8);
        const int row = idx >> 3, c = idx & 7;
        cp16(sa0 + B_OFF + row * 128 + ((c ^ (row & 7)) << 4),
             W + (size_t)(bn + row) * (size_t)K + K0 + c * 8, 16);
    }
}

__global__ void __launch_bounds__(256, 1) gemm_tc(
    GJob j0, GJob j1, GJob j2, int c0, int c1)
{
    extern __shared__ float smbuf[];
    const uint32_t smem_base = (uint32_t)__cvta_generic_to_shared(smbuf);

    // ---- job decode ----
    GJob J;
    int local;
    {
        const int id = blockIdx.x;
        if (id < c0)      { J = j0; local = id; }
        else if (id < c1) { J = j1; local = id - c0; }
        else              { J = j2; local = id - c1; }
    }
    const int bnb = J.N >> 7;
    const int bm = (local / bnb) << 8, bn = (local % bnb) << 7;

    const int tid  = threadIdx.x;
    const int warp = tid >> 5, lane = tid & 31;
    const int wm   = (warp >> 1) << 6, wn = (warp & 1) << 6;
    const int lg   = lane >> 2, la3 = lane & 3;

    // ldmatrix per-lane constants
    const int l7 = lane & 7, lq = lane >> 3;
    uint32_t arow[4], brow[4];
#pragma unroll
    for (int mt = 0; mt < 4; mt++)
        arow[mt] = (uint32_t)((wm + mt * 16 + ((lq & 1) << 3) + l7) * 128);
    const int a_kq = lq >> 1;
#pragma unroll
    for (int p = 0; p < 4; p++)
        brow[p] = (uint32_t)(B_OFF + (wn + p * 16 + ((lq >> 1) << 3) + l7) * 128);
    const int b_kq = lq & 1;

    float4 acc[4][8];
#pragma unroll
    for (int i = 0; i < 4; i++)
#pragma unroll
        for (int j = 0; j < 8; j++) acc[i][j] = make_float4(0.f, 0.f, 0.f, 0.f);

    const int nkb = J.K >> 6;
    issue_tile(smem_base,             J.A, J.W, bm, bn,  0, J.lda, J.K, J.im2col, tid);
    CP_COMMIT();
    issue_tile(smem_base + STG_BYTES, J.A, J.W, bm, bn, 64, J.lda, J.K, J.im2col, tid);
    CP_COMMIT();

    for (int kb = 0; kb < nkb; kb++) {
        asm volatile("cp.async.wait_group 1;");
        __syncthreads();

        const uint32_t Ab = smem_base + (kb & 1) * STG_BYTES;
#pragma unroll
        for (int ks = 0; ks < 4; ks++) {
            const uint32_t axor = (uint32_t)((((ks << 1) + a_kq) ^ l7) << 4);
            const uint32_t bxor = (uint32_t)((((ks << 1) + b_kq) ^ l7) << 4);
            uint32_t af[4][4], bf[4][4];
#pragma unroll
            for (int mt = 0; mt < 4; mt++) ldsm4(af[mt], Ab + arow[mt] + axor);
#pragma unroll
            for (int p = 0; p < 4; p++)    ldsm4(bf[p],  Ab + brow[p] + bxor);
#pragma unroll
            for (int mt = 0; mt < 4; mt++)
#pragma unroll
                for (int p = 0; p < 4; p++) {
                    mma16(acc[mt][2 * p],     af[mt], &bf[p][0]);
                    mma16(acc[mt][2 * p + 1], af[mt], &bf[p][2]);
                }
        }
        __syncthreads();
        if (kb + 2 < nkb)
            issue_tile(Ab, J.A, J.W, bm, bn, (kb + 2) << 6, J.lda, J.K, J.im2col, tid);
        CP_COMMIT();
    }

    // ---------------- epilogue ----------------
#pragma unroll
    for (int mt = 0; mt < 4; mt++) {
        const int m0 = bm + wm + (mt << 4) + lg;
#pragma unroll
        for (int nt = 0; nt < 8; nt++) {
            const int n = bn + wn + (nt << 3) + (la3 << 1);
            const float b0 = J.bias[n], b1 = J.bias[n + 1];
            float v[4] = {acc[mt][nt].x + b0, acc[mt][nt].y + b1,
                          acc[mt][nt].z + b0, acc[mt][nt].w + b1};
#pragma unroll
            for (int h = 0; h < 2; h++) {
                const int m = m0 + h * 8;
                if (J.mode == 3) {
                    float x0 = v[h * 2], x1 = v[h * 2 + 1];
                    x0 = 0.5f * x0 * (1.f + erff(x0 * 0.70710678118654752f));
                    x1 = 0.5f * x1 * (1.f + erff(x1 * 0.70710678118654752f));
                    *reinterpret_cast<__half2*>(
                        reinterpret_cast<__half*>(J.C) + (size_t)m * (size_t)J.N + n) =
                        __floats2half2_rn(x0, x1);
                } else {
#pragma unroll
                    for (int j = 0; j < 2; j++) {
                        float x = v[h * 2 + j];
                        const int nn = n + j;
                        if (J.mode == 1) x *= J.scale;
                        else if (J.mode == 2) x = fmaxf(x, 0.f);
                        else if (J.mode == 4) x += J.R[((size_t)(m >> 12) * 256 + nn) * 4096 + (m & 4095)];
                        else if (J.mode == 5) x += J.R[(size_t)m * 256 + nn];
                        if (J.mode == 5)
                            J.C[((size_t)(m >> 12) * 256 + nn) * 4096 + (m & 4095)] = x;
                        else
                            J.C[(size_t)m * (size_t)J.N + nn] = x;
                    }
                }
            }
        }
    }
}

// ---------------- offset head ----------------
__global__ void off2_k(const float* __restrict__ h1, const float* __restrict__ w,
                       const float* __restrict__ bias, float* __restrict__ offs) {
    int id = blockIdx.x * blockDim.x + threadIdx.x;
    if (id >= MTOT * 18) return;
    int m = id / 18, n = id - m * 18;
    const float4* a = reinterpret_cast<const float4*>(h1 + (size_t)m * 256);
    const float4* ww = reinterpret_cast<const float4*>(w + (size_t)n * 256);
    float s = bias[n];
#pragma unroll 8
    for (int k = 0; k < 64; k++) {
        float4 av = a[k], wv = ww[k];
        s += av.x * wv.x + av.y * wv.y + av.z * wv.z + av.w * wv.w;
    }
    offs[id] = s;
}

// ---------------- fused bilinear-sample + 9-way attention (fp16 out) ----------------
#define LOAD8(dst, ptr)                                                     \
    {                                                                       \
        float4 _u0 = *reinterpret_cast<const float4*>(ptr);                 \
        float4 _u1 = *reinterpret_cast<const float4*>((ptr) + 4);           \
        dst[0] = _u0.x; dst[1] = _u0.y; dst[2] = _u0.z; dst[3] = _u0.w;     \
        dst[4] = _u1.x; dst[5] = _u1.y; dst[6] = _u1.z; dst[7] = _u1.w;     \
    }

__global__ void __launch_bounds__(256) attn_k(
    const float* __restrict__ qb, const float* __restrict__ kv,
    const float* __restrict__ offs, __half* __restrict__ outp) {
    __shared__ float sh[8][9][8];
    const int warp = threadIdx.x >> 5, lane = threadIdx.x & 31;
    const int p = blockIdx.x * 8 + warp;
    const int b = p >> 12, s = p & 4095, y = s >> 6, x = s & 63;
    const float* kvb = kv + (((size_t)b << 12) << 9);

    float qr[8];
    LOAD8(qr, qb + (size_t)p * 256 + lane * 8);

    for (int o = 0; o < 9; o++) {
        int ys = y + o / 3 - 1, xs = x + o % 3 - 1;
        float prod[8] = {0.f, 0.f, 0.f, 0.f, 0.f, 0.f, 0.f, 0.f};
        if (ys >= 0 && ys < 64 && xs >= 0 && xs < 64) {
            const float* op = offs + (size_t)((b << 12) + (ys << 6) + xs) * 18 + 2 * o;
            float px = op[0], py = op[1];
            float y0f = floorf(py), x0f = floorf(px);
            float wy = py - y0f, wx = px - x0f;
            int y0 = (int)y0f, x0 = (int)x0f;
            float w00 = (1.f - wy) * (1.f - wx), w01 = (1.f - wy) * wx;
            float w10 = wy * (1.f - wx), w11 = wy * wx;
            bool vy0 = (y0 >= 0) && (y0 < 64), vy1 = (y0 + 1 >= 0) && (y0 + 1 < 64);
            bool vx0 = (x0 >= 0) && (x0 < 64), vx1 = (x0 + 1 >= 0) && (x0 + 1 < 64);
            w00 = (vy0 && vx0) ? w00 : 0.f; w01 = (vy0 && vx1) ? w01 : 0.f;
            w10 = (vy1 && vx0) ? w10 : 0.f; w11 = (vy1 && vx1) ? w11 : 0.f;
            int y0c = min(max(y0, 0), 63), y1c = min(max(y0 + 1, 0), 63);
            int x0c = min(max(x0, 0), 63), x1c = min(max(x0 + 1, 0), 63);
            float c00[8], c01[8], c10[8], c11[8];
            LOAD8(c00, kvb + ((size_t)((y0c << 6) + x0c) << 9) + lane * 8);
            LOAD8(c01, kvb + ((size_t)((y0c << 6) + x1c) << 9) + lane * 8);
            LOAD8(c10, kvb + ((size_t)((y1c << 6) + x0c) << 9) + lane * 8);
            LOAD8(c11, kvb + ((size_t)((y1c << 6) + x1c) << 9) + lane * 8);
#pragma unroll
            for (int h = 0; h < 8; h++) {
                float kvv = w00 * c00[h] + w01 * c01[h] + w10 * c10[h] + w11 * c11[h];
                prod[h] = qr[h] * kvv;
            }
        }
#pragma unroll
        for (int off = 16; off > 0; off >>= 1)
#pragma unroll
            for (int h = 0; h < 8; h++)
                prod[h] += __shfl_xor_sync(0xffffffffu, prod[h], off);
        if (lane == 0) {
#pragma unroll
            for (int h = 0; h < 8; h++) sh[warp][o][h] = prod[h];
        }
    }
    __syncwarp();
    if (lane < 8) {
        float e[9]; float mx = -1e30f;
#pragma unroll
        for (int o = 0; o < 9; o++) { e[o] = sh[warp][o][lane]; mx = fmaxf(mx, e[o]); }
        float sm = 0.f;
#pragma unroll
        for (int o = 0; o < 9; o++) { e[o] = expf(e[o] - mx); sm += e[o]; }
        float inv = 1.f / sm;
#pragma unroll
        for (int o = 0; o < 9; o++) sh[warp][o][lane] = e[o] * inv;
    }
    __syncwarp();
    float acc[8] = {0.f, 0.f, 0.f, 0.f, 0.f, 0.f, 0.f, 0.f};
    for (int o = 0; o < 9; o++) {
        int ys = y + o / 3 - 1, xs = x + o % 3 - 1;
        if (ys < 0 || ys >= 64 || xs < 0 || xs >= 64) continue;
        const float* op = offs + (size_t)((b << 12) + (ys << 6) + xs) * 18 + 2 * o;
        float px = op[0], py = op[1];
        float y0f = floorf(py), x0f = floorf(px);
        float wy = py - y0f, wx = px - x0f;
        int y0 = (int)y0f, x0 = (int)x0f;
        float w00 = (1.f - wy) * (1.f - wx), w01 = (1.f - wy) * wx;
        float w10 = wy * (1.f - wx), w11 = wy * wx;
        bool vy0 = (y0 >= 0) && (y0 < 64), vy1 = (y0 + 1 >= 0) && (y0 + 1 < 64);
        bool vx0 = (x0 >= 0) && (x0 < 64), vx1 = (x0 + 1 >= 0) && (x0 + 1 < 64);
        w00 = (vy0 && vx0) ? w00 : 0.f; w01 = (vy0 && vx1) ? w01 : 0.f;
        w10 = (vy1 && vx0) ? w10 : 0.f; w11 = (vy1 && vx1) ? w11 : 0.f;
        int y0c = min(max(y0, 0), 63), y1c = min(max(y0 + 1, 0), 63);
        int x0c = min(max(x0, 0), 63), x1c = min(max(x0 + 1, 0), 63);
        float c00[8], c01[8], c10[8], c11[8];
        LOAD8(c00, kvb + ((size_t)((y0c << 6) + x0c) << 9) + 256 + lane * 8);
        LOAD8(c01, kvb + ((size_t)((y0c << 6) + x1c) << 9) + 256 + lane * 8);
        LOAD8(c10, kvb + ((size_t)((y1c << 6) + x0c) << 9) + 256 + lane * 8);
        LOAD8(c11, kvb + ((size_t)((y1c << 6) + x1c) << 9) + 256 + lane * 8);
#pragma unroll
        for (int h = 0; h < 8; h++) {
            float vv = w00 * c00[h] + w01 * c01[h] + w10 * c10[h] + w11 * c11[h];
            acc[h] += sh[warp][o][h] * vv;
        }
    }
    __half2 h0 = __floats2half2_rn(acc[0], acc[1]);
    __half2 h1 = __floats2half2_rn(acc[2], acc[3]);
    __half2 h2 = __floats2half2_rn(acc[4], acc[5]);
    __half2 h3 = __floats2half2_rn(acc[6], acc[7]);
    uint4 pk;
    pk.x = *reinterpret_cast<uint32_t*>(&h0);
    pk.y = *reinterpret_cast<uint32_t*>(&h1);
    pk.z = *reinterpret_cast<uint32_t*>(&h2);
    pk.w = *reinterpret_cast<uint32_t*>(&h3);
    *reinterpret_cast<uint4*>(outp + (size_t)p * 256 + lane * 8) = pk;
}

// ---------------- host ----------------
extern "C" void kernel_launch(void* const* d_in, const int* in_sizes, int n_in,
                              void* d_out, int out_size) {
    const float* x_q    = (const float*)d_in[0];
    const float* x_kv   = (const float*)d_in[1];
    const float* n1w    = (const float*)d_in[2];
    const float* n1b    = (const float*)d_in[3];
    const float* q_w    = (const float*)d_in[4];
    const float* q_b    = (const float*)d_in[5];
    const float* kv_w   = (const float*)d_in[6];
    const float* kv_b   = (const float*)d_in[7];
    const float* off1_w = (const float*)d_in[8];
    const float* off1_b = (const float*)d_in[9];
    const float* off2_w = (const float*)d_in[10];
    const float* off2_b = (const float*)d_in[11];
    const float* proj_w = (const float*)d_in[12];
    const float* proj_b = (const float*)d_in[13];
    const float* n2w    = (const float*)d_in[14];
    const float* n2b    = (const float*)d_in[15];
    const float* fc1_w  = (const float*)d_in[16];
    const float* fc1_b  = (const float*)d_in[17];
    const float* fc2_w  = (const float*)d_in[18];
    const float* fc2_b  = (const float*)d_in[19];
    float* out = (float*)d_out;

    __half *xall, *att, *xn2, *hid, *wr, *wh;
    float *qb, *kvb, *h1, *offs, *xres, *st1, *st2;
    float2* part;
    cudaGetSymbolAddress((void**)&xall, g_xall);
    cudaGetSymbolAddress((void**)&qb,   g_q);
    cudaGetSymbolAddress((void**)&kvb,  g_kv);
    cudaGetSymbolAddress((void**)&h1,   g_h1);
    cudaGetSymbolAddress((void**)&offs, g_offs);
    cudaGetSymbolAddress((void**)&att,  g_att);
    cudaGetSymbolAddress((void**)&xres, g_xres);
    cudaGetSymbolAddress((void**)&xn2,  g_xn2);
    cudaGetSymbolAddress((void**)&hid,  g_hid);
    cudaGetSymbolAddress((void**)&wr,   g_wr);
    cudaGetSymbolAddress((void**)&wh,   g_wh);
    cudaGetSymbolAddress((void**)&part, g_part);
    cudaGetSymbolAddress((void**)&st1,  g_st1);
    cudaGetSymbolAddress((void**)&st2,  g_st2);

    __half* qwh  = wh;
    __half* kvwh = qwh  + 65536;
    __half* pwh  = kvwh + 131072;
    __half* f1wh = pwh  + 65536;
    __half* f2wh = f1wh + 262144;

    cudaFuncSetAttribute(gemm_tc, cudaFuncAttributeMaxDynamicSharedMemorySize, SMEM_REQ);

    prep_k<<<7680, 256>>>(off1_w, wr, q_w, qwh, kv_w, kvwh, proj_w, pwh,
                          fc1_w, f1wh, fc2_w, f2wh);
    gn_p1<<<256, 256>>>(x_q, x_kv, part);
    gn_p2<<<1, 256>>>(part, st1, 8);
    norm_pack_k<<<dim3(128, 8, 8), dim3(32, 8)>>>(x_q, x_kv, st1, n1w, n1b, xall);

    GJob zero = {};
    // fused q + kv + conv (conv first). M-blocks = 64 (256 rows each).
    {
        GJob jc  = {xall,       wr,   off1_b, h1,  nullptr, 256, 4608, 512, 2, 1, 0.f};
        GJob jkv = {xall + 256, kvwh, kv_b,   kvb, nullptr, 512, 256,  512, 0, 0, 0.f};
        GJob jq  = {xall,       qwh,  q_b,    qb,  nullptr, 256, 256,  512, 1, 0,
                    0.17677669529663689f};
        gemm_tc<<<512, 256, SMEM_REQ>>>(jc, jkv, jq, 128, 384);
    }
    off2_k<<<(MTOT * 18) / 256, 256>>>(h1, off2_w, off2_b, offs);
    attn_k<<<2048, 256>>>(qb, kvb, offs, att);
    // xres = x_q + att @ proj_w^T + b
    {
        GJob jp = {att, pwh, proj_b, xres, x_q, 256, 256, 256, 4, 0, 0.f};
        gemm_tc<<<128, 256, SMEM_REQ>>>(jp, zero, zero, 128, 128);
    }
    gn_p1<<<128, 256>>>(xres, xres, part);
    gn_p2<<<1, 256>>>(part, st2, 4);
    norm2_k<<<(MTOT * 256) / 256, 256>>>(xres, st2, n2w, n2b, xn2);
    // hid = gelu(xn2 @ fc1_w^T + b) -> half
    {
        GJob jf1 = {xn2, f1wh, fc1_b, (float*)hid, nullptr, 1024, 256, 256, 3, 0, 0.f};
        gemm_tc<<<512, 256, SMEM_REQ>>>(jf1, zero, zero, 512, 512);
    }
    // out(NCHW) = xres + hid @ fc2_w^T + b
    {
        GJob jf2 = {hid, f2wh, fc2_b, out, xres, 256, 1024, 1024, 5, 0, 0.f};
        gemm_tc<<<128, 256, SMEM_REQ>>>(jf2, zero, zero, 128, 128);
    }
}

// round 10
// speedup vs baseline: 1.3728x; 1.3728x over previous
#include <cuda_runtime.h>
#include <cuda_fp16.h>
#include <math.h>
#include <stdint.h>

#define MTOT 16384

// ---------------- scratch ----------------
__device__ __align__(1024) __half g_xall[(size_t)MTOT * 512];
__device__ float  g_q   [(size_t)MTOT * 256];
__device__ __align__(1024) __half g_kv  [(size_t)MTOT * 512];
__device__ float  g_h1  [(size_t)MTOT * 256];
__device__ float  g_offs[(size_t)MTOT * 18];
__device__ __align__(1024) __half g_att [(size_t)MTOT * 256];
__device__ float  g_xres[(size_t)MTOT * 256];
__device__ __align__(1024) __half g_xn2 [(size_t)MTOT * 256];
__device__ __align__(1024) __half g_hid [(size_t)MTOT * 1024];
__device__ __align__(1024) __half g_wr  [256 * 4608];
__device__ __align__(1024) __half g_wh  [65536 + 131072 + 65536 + 262144 + 262144];
__device__ float2 g_part[256];
__device__ float  g_st1 [16];
__device__ float  g_st2 [8];

// ---------------- fused weight prep: conv repack + 5x f2h ----------------
__global__ void prep_k(const float* __restrict__ off1_w, __half* __restrict__ wr,
                       const float* __restrict__ q_w,    __half* __restrict__ qwh,
                       const float* __restrict__ kv_w,   __half* __restrict__ kvwh,
                       const float* __restrict__ proj_w, __half* __restrict__ pwh,
                       const float* __restrict__ fc1_w,  __half* __restrict__ f1wh,
                       const float* __restrict__ fc2_w,  __half* __restrict__ f2wh) {
    int id = blockIdx.x * 256 + threadIdx.x;
    if (id < 1179648) {
        int o = id / 4608, k = id - o * 4608;
        int nb = k >> 9, c = k & 511;
        int ky = nb / 3, kx = nb - ky * 3;
        wr[id] = __float2half(off1_w[((size_t)o * 512 + c) * 9 + ky * 3 + kx]);
        return;
    }
    id -= 1179648;
    if (id < 65536)  { qwh [id] = __float2half(q_w [id]); return; }  id -= 65536;
    if (id < 131072) { kvwh[id] = __float2half(kv_w[id]); return; }  id -= 131072;
    if (id < 65536)  { pwh [id] = __float2half(proj_w[id]); return; } id -= 65536;
    if (id < 262144) { f1wh[id] = __float2half(fc1_w[id]); return; }  id -= 262144;
    f2wh[id] = __float2half(fc2_w[id]);
}

// ---------------- groupnorm stats: phase 1 ----------------
__global__ void gn_p1(const float* __restrict__ A, const float* __restrict__ B2,
                      float2* __restrict__ part) {
    int bi = blockIdx.x;
    int slab = bi >> 5, chunk = bi & 31;
    int tensor = slab >> 2, batch = slab & 3;
    const float* src = (tensor ? B2 : A) + ((size_t)batch << 20) + ((size_t)chunk << 15);
    const float4* p4 = reinterpret_cast<const float4*>(src);
    float s = 0.f, s2 = 0.f;
    for (int i = threadIdx.x; i < 8192; i += 256) {
        float4 v = p4[i];
        s  += v.x + v.y + v.z + v.w;
        s2 += v.x * v.x + v.y * v.y + v.z * v.z + v.w * v.w;
    }
    __shared__ float sh1[256], sh2[256];
    sh1[threadIdx.x] = s; sh2[threadIdx.x] = s2;
    __syncthreads();
    for (int st = 128; st > 0; st >>= 1) {
        if (threadIdx.x < st) { sh1[threadIdx.x] += sh1[threadIdx.x + st];
                                sh2[threadIdx.x] += sh2[threadIdx.x + st]; }
        __syncthreads();
    }
    if (threadIdx.x == 0) part[slab * 32 + chunk] = make_float2(sh1[0], sh2[0]);
}

// ---------------- groupnorm stats: phase 2 ----------------
__global__ void gn_p2(const float2* __restrict__ part, float* __restrict__ stats, int nslab) {
    int slab = threadIdx.x >> 5, lane = threadIdx.x & 31;
    if (slab >= nslab) return;
    float2 v = part[slab * 32 + lane];
    float s = v.x, s2 = v.y;
#pragma unroll
    for (int off = 16; off > 0; off >>= 1) {
        s  += __shfl_xor_sync(0xffffffffu, s,  off);
        s2 += __shfl_xor_sync(0xffffffffu, s2, off);
    }
    if (lane == 0) {
        float inv = 1.f / 1048576.f;
        float mu = s * inv;
        float var = s2 * inv - mu * mu;
        stats[slab * 2] = mu;
        stats[slab * 2 + 1] = rsqrtf(var + 1e-5f);
    }
}

// ---------------- normalize + NCHW->NHWC pack (fp16 out) ----------------
__global__ void norm_pack_k(const float* __restrict__ xq, const float* __restrict__ xkv,
                            const float* __restrict__ stats, const float* __restrict__ w,
                            const float* __restrict__ bb, __half* __restrict__ xall) {
    __shared__ float tile[32][33];
    int bz = blockIdx.z;
    int tensor = bz >> 2, batch = bz & 3;
    const float* src = (tensor == 0 ? xq : xkv) + ((size_t)batch << 20);
    float mu = stats[bz * 2], rstd = stats[bz * 2 + 1];
    int s0 = blockIdx.x * 32, c0 = blockIdx.y * 32;
    int tx = threadIdx.x, ty = threadIdx.y;
#pragma unroll
    for (int k = 0; k < 4; k++) {
        int c = c0 + ty + k * 8;
        tile[ty + k * 8][tx] = src[(size_t)c * 4096 + s0 + tx];
    }
    __syncthreads();
#pragma unroll
    for (int k = 0; k < 4; k++) {
        int sl = ty + k * 8;
        int c = c0 + tx;
        float v = (tile[tx][sl] - mu) * rstd * w[c] + bb[c];
        xall[(((size_t)batch * 4096 + s0 + sl) << 9) + tensor * 256 + c] = __float2half(v);
    }
}

// ---------------- norm2 (fp16 out) ----------------
__global__ void norm2_k(const float* __restrict__ xres, const float* __restrict__ stats,
                        const float* __restrict__ w, const float* __restrict__ bb,
                        __half* __restrict__ xn) {
    int id = blockIdx.x * blockDim.x + threadIdx.x;
    if (id >= MTOT * 256) return;
    int b = id >> 20, c = id & 255;
    xn[id] = __float2half((xres[id] - stats[b * 2]) * stats[b * 2 + 1] * w[c] + bb[c]);
}

// ---------------- PTX helpers ----------------
__device__ __forceinline__ void mma16(float4& d, const uint32_t* a, const uint32_t* b) {
    asm volatile("mma.sync.aligned.m16n8k16.row.col.f32.f16.f16.f32 "
        "{%0,%1,%2,%3}, {%4,%5,%6,%7}, {%8,%9}, {%0,%1,%2,%3};\n"
        : "+f"(d.x), "+f"(d.y), "+f"(d.z), "+f"(d.w)
        : "r"(a[0]), "r"(a[1]), "r"(a[2]), "r"(a[3]), "r"(b[0]), "r"(b[1]));
}
__device__ __forceinline__ void ldsm4(uint32_t* r, uint32_t a) {
    asm volatile("ldmatrix.sync.aligned.m8n8.x4.shared.b16 {%0,%1,%2,%3}, [%4];"
        : "=r"(r[0]), "=r"(r[1]), "=r"(r[2]), "=r"(r[3]) : "r"(a));
}
__device__ __forceinline__ void cp16(uint32_t d, const void* s, int sz) {
    asm volatile("cp.async.cg.shared.global [%0], [%1], 16, %2;"
        :: "r"(d), "l"(s), "r"(sz));
}
#define CP_COMMIT() asm volatile("cp.async.commit_group;")

// ---------------- multi-job fp16 tensor-core GEMM (R7 config) ----------------
// C[M,N] = A[M,K] @ W[N,K]^T + bias (A, W fp16; accum/bias fp32). M = 16384.
// mode 0 plain / 1 *scale / 2 relu / 3 gelu->HALF / 4 +R(NCHW)->NHWC / 5 +R(NHWC)->NCHW
// mode 6 plain->HALF
// CTA tile 128x128x64(halves), 256 thr, 3-stage cp.async, mma m16n8k16, 2 CTA/SM.
#define STG_BYTES 32768
#define SMEM_REQ  (3 * STG_BYTES)

struct GJob {
    const __half* A; const __half* W; const float* bias; float* C; const float* R;
    int N, K, lda, mode, im2col; float scale;
};

__device__ __forceinline__ void issue_tile(
    uint32_t sa0, const __half* __restrict__ A, const __half* __restrict__ W,
    int bm, int bn, int K0, int lda, int K, int im2col, int lrow, int g)
{
    uint32_t sa = sa0 + lrow * 128;
    const __half* srcA; int szA = 16;
    if (!im2col) {
        srcA = A + (size_t)(bm + lrow) * lda + K0;
    } else {
        const int gm = bm + lrow;
        const int ib = gm >> 12, sp = gm & 4095;
        const int iy = sp >> 6, ix = sp & 63;
        const int nb = K0 >> 9, cc0 = K0 & 511;
        const int qy = nb / 3;
        const int yy = iy + qy - 1, xx = ix + (nb - qy * 3) - 1;
        srcA = A + (((size_t)(ib << 12) + (yy << 6) + xx) << 9) + cc0;
        if (!(yy >= 0 && yy < 64 && xx >= 0 && xx < 64)) { szA = 0; srcA = A; }
    }
    const __half* srcB = W + (size_t)(bn + lrow) * (size_t)K + K0;
    const int r7 = lrow & 7;
#pragma unroll
    for (int j = 0; j < 4; j++) {
        const int c = g + j;
        const uint32_t off = (uint32_t)((c ^ r7) << 4);
        cp16(sa + off, srcA + c * 8, szA);
        cp16(sa + 16384 + off, srcB + c * 8, 16);
    }
}

__global__ void __launch_bounds__(256, 2) gemm_tc(
    GJob j0, GJob j1, GJob j2, int c0, int c1)
{
    extern __shared__ float smbuf[];
    const uint32_t smem_base = (uint32_t)__cvta_generic_to_shared(smbuf);

    GJob J;
    int local;
    {
        const int id = blockIdx.x;
        if (id < c0)      { J = j0; local = id; }
        else if (id < c1) { J = j1; local = id - c0; }
        else              { J = j2; local = id - c1; }
    }
    const int bnb = J.N >> 7;
    const int bm = (local / bnb) << 7, bn = (local % bnb) << 7;

    const int tid  = threadIdx.x;
    const int warp = tid >> 5, lane = tid & 31;
    const int wm   = (warp >> 2) << 6, wn = (warp & 3) << 5;
    const int lg   = lane >> 2, la3 = lane & 3;

    const int lrow = tid >> 1, g = (tid & 1) * 4;

    const int l7 = lane & 7, lq = lane >> 3;
    uint32_t arow[4], brow[2];
#pragma unroll
    for (int mt = 0; mt < 4; mt++)
        arow[mt] = (uint32_t)((wm + mt * 16 + ((lq & 1) << 3) + l7) * 128);
    const int a_kq = lq >> 1;
#pragma unroll
    for (int p = 0; p < 2; p++)
        brow[p] = (uint32_t)(16384 + (wn + p * 16 + ((lq >> 1) << 3) + l7) * 128);
    const int b_kq = lq & 1;

    float4 acc[4][4];
#pragma unroll
    for (int i = 0; i < 4; i++)
#pragma unroll
        for (int j = 0; j < 4; j++) acc[i][j] = make_float4(0.f, 0.f, 0.f, 0.f);

    const int nkb = J.K >> 6;
    issue_tile(smem_base,             J.A, J.W, bm, bn,  0, J.lda, J.K, J.im2col, lrow, g);
    CP_COMMIT();
    issue_tile(smem_base + STG_BYTES, J.A, J.W, bm, bn, 64, J.lda, J.K, J.im2col, lrow, g);
    CP_COMMIT();

    int stg = 0;
    for (int kb = 0; kb < nkb; kb++) {
        asm volatile("cp.async.wait_group 1;");
        __syncthreads();
        if (kb + 2 < nkb) {
            int s2 = stg + 2; if (s2 >= 3) s2 -= 3;
            issue_tile(smem_base + s2 * STG_BYTES, J.A, J.W, bm, bn,
                       (kb + 2) << 6, J.lda, J.K, J.im2col, lrow, g);
        }
        CP_COMMIT();

        const uint32_t Ab = smem_base + stg * STG_BYTES;
#pragma unroll
        for (int ks = 0; ks < 4; ks++) {
            const uint32_t axor = (uint32_t)((((ks << 1) + a_kq) ^ l7) << 4);
            const uint32_t bxor = (uint32_t)((((ks << 1) + b_kq) ^ l7) << 4);
            uint32_t af[4][4], bf[2][4];
#pragma unroll
            for (int mt = 0; mt < 4; mt++) ldsm4(af[mt], Ab + arow[mt] + axor);
#pragma unroll
            for (int p = 0; p < 2; p++)    ldsm4(bf[p],  Ab + brow[p] + bxor);
#pragma unroll
            for (int mt = 0; mt < 4; mt++) {
                mma16(acc[mt][0], af[mt], &bf[0][0]);
                mma16(acc[mt][1], af[mt], &bf[0][2]);
                mma16(acc[mt][2], af[mt], &bf[1][0]);
                mma16(acc[mt][3], af[mt], &bf[1][2]);
            }
        }
        if (++stg == 3) stg = 0;
    }

    // ---------------- epilogue ----------------
#pragma unroll
    for (int mt = 0; mt < 4; mt++) {
        const int m0 = bm + wm + (mt << 4) + lg;
#pragma unroll
        for (int nt = 0; nt < 4; nt++) {
            const int n = bn + wn + (nt << 3) + (la3 << 1);
            const float b0 = J.bias[n], b1 = J.bias[n + 1];
            float v[4] = {acc[mt][nt].x + b0, acc[mt][nt].y + b1,
                          acc[mt][nt].z + b0, acc[mt][nt].w + b1};
#pragma unroll
            for (int h = 0; h < 2; h++) {
                const int m = m0 + h * 8;
                if (J.mode == 3 || J.mode == 6) {
                    float x0 = v[h * 2], x1 = v[h * 2 + 1];
                    if (J.mode == 3) {
                        x0 = 0.5f * x0 * (1.f + erff(x0 * 0.70710678118654752f));
                        x1 = 0.5f * x1 * (1.f + erff(x1 * 0.70710678118654752f));
                    }
                    *reinterpret_cast<__half2*>(
                        reinterpret_cast<__half*>(J.C) + (size_t)m * (size_t)J.N + n) =
                        __floats2half2_rn(x0, x1);
                } else {
#pragma unroll
                    for (int j = 0; j < 2; j++) {
                        float x = v[h * 2 + j];
                        const int nn = n + j;
                        if (J.mode == 1) x *= J.scale;
                        else if (J.mode == 2) x = fmaxf(x, 0.f);
                        else if (J.mode == 4) x += J.R[((size_t)(m >> 12) * 256 + nn) * 4096 + (m & 4095)];
                        else if (J.mode == 5) x += J.R[(size_t)m * 256 + nn];
                        if (J.mode == 5)
                            J.C[((size_t)(m >> 12) * 256 + nn) * 4096 + (m & 4095)] = x;
                        else
                            J.C[(size_t)m * (size_t)J.N + nn] = x;
                    }
                }
            }
        }
    }
}

// ---------------- offset head ----------------
__global__ void off2_k(const float* __restrict__ h1, const float* __restrict__ w,
                       const float* __restrict__ bias, float* __restrict__ offs) {
    int id = blockIdx.x * blockDim.x + threadIdx.x;
    if (id >= MTOT * 18) return;
    int m = id / 18, n = id - m * 18;
    const float4* a = reinterpret_cast<const float4*>(h1 + (size_t)m * 256);
    const float4* ww = reinterpret_cast<const float4*>(w + (size_t)n * 256);
    float s = bias[n];
#pragma unroll 8
    for (int k = 0; k < 64; k++) {
        float4 av = a[k], wv = ww[k];
        s += av.x * wv.x + av.y * wv.y + av.z * wv.z + av.w * wv.w;
    }
    offs[id] = s;
}

// ---------------- fused bilinear-sample + 9-way attention (fp16 kv, fp16 out) ----------------
#define LOAD8(dst, ptr)                                                     \
    {                                                                       \
        float4 _u0 = *reinterpret_cast<const float4*>(ptr);                 \
        float4 _u1 = *reinterpret_cast<const float4*>((ptr) + 4);           \
        dst[0] = _u0.x; dst[1] = _u0.y; dst[2] = _u0.z; dst[3] = _u0.w;     \
        dst[4] = _u1.x; dst[5] = _u1.y; dst[6] = _u1.z; dst[7] = _u1.w;     \
    }
#define LOAD8H(dst, ptr)                                                    \
    {                                                                       \
        uint4 _u = *reinterpret_cast<const uint4*>(ptr);                    \
        __half2* _hh = reinterpret_cast<__half2*>(&_u);                     \
        float2 _f0 = __half22float2(_hh[0]), _f1 = __half22float2(_hh[1]);  \
        float2 _f2 = __half22float2(_hh[2]), _f3 = __half22float2(_hh[3]);  \
        dst[0] = _f0.x; dst[1] = _f0.y; dst[2] = _f1.x; dst[3] = _f1.y;     \
        dst[4] = _f2.x; dst[5] = _f2.y; dst[6] = _f3.x; dst[7] = _f3.y;     \
    }

__global__ void __launch_bounds__(256) attn_k(
    const float* __restrict__ qb, const __half* __restrict__ kv,
    const float* __restrict__ offs, __half* __restrict__ outp) {
    __shared__ float sh[8][9][8];
    const int warp = threadIdx.x >> 5, lane = threadIdx.x & 31;
    const int p = blockIdx.x * 8 + warp;
    const int b = p >> 12, s = p & 4095, y = s >> 6, x = s & 63;
    const __half* kvb = kv + (((size_t)b << 12) << 9);

    float qr[8];
    LOAD8(qr, qb + (size_t)p * 256 + lane * 8);

    for (int o = 0; o < 9; o++) {
        int ys = y + o / 3 - 1, xs = x + o % 3 - 1;
        float prod[8] = {0.f, 0.f, 0.f, 0.f, 0.f, 0.f, 0.f, 0.f};
        if (ys >= 0 && ys < 64 && xs >= 0 && xs < 64) {
            const float* op = offs + (size_t)((b << 12) + (ys << 6) + xs) * 18 + 2 * o;
            float px = op[0], py = op[1];
            float y0f = floorf(py), x0f = floorf(px);
            float wy = py - y0f, wx = px - x0f;
            int y0 = (int)y0f, x0 = (int)x0f;
            float w00 = (1.f - wy) * (1.f - wx), w01 = (1.f - wy) * wx;
            float w10 = wy * (1.f - wx), w11 = wy * wx;
            bool vy0 = (y0 >= 0) && (y0 < 64), vy1 = (y0 + 1 >= 0) && (y0 + 1 < 64);
            bool vx0 = (x0 >= 0) && (x0 < 64), vx1 = (x0 + 1 >= 0) && (x0 + 1 < 64);
            w00 = (vy0 && vx0) ? w00 : 0.f; w01 = (vy0 && vx1) ? w01 : 0.f;
            w10 = (vy1 && vx0) ? w10 : 0.f; w11 = (vy1 && vx1) ? w11 : 0.f;
            int y0c = min(max(y0, 0), 63), y1c = min(max(y0 + 1, 0), 63);
            int x0c = min(max(x0, 0), 63), x1c = min(max(x0 + 1, 0), 63);
            float c00[8], c01[8], c10[8], c11[8];
            LOAD8H(c00, kvb + ((size_t)((y0c << 6) + x0c) << 9) + lane * 8);
            LOAD8H(c01, kvb + ((size_t)((y0c << 6) + x1c) << 9) + lane * 8);
            LOAD8H(c10, kvb + ((size_t)((y1c << 6) + x0c) << 9) + lane * 8);
            LOAD8H(c11, kvb + ((size_t)((y1c << 6) + x1c) << 9) + lane * 8);
#pragma unroll
            for (int h = 0; h < 8; h++) {
                float kvv = w00 * c00[h] + w01 * c01[h] + w10 * c10[h] + w11 * c11[h];
                prod[h] = qr[h] * kvv;
            }
        }
#pragma unroll
        for (int off = 16; off > 0; off >>= 1)
#pragma unroll
            for (int h = 0; h < 8; h++)
                prod[h] += __shfl_xor_sync(0xffffffffu, prod[h], off);
        if (lane == 0) {
#pragma unroll
            for (int h = 0; h < 8; h++) sh[warp][o][h] = prod[h];
        }
    }
    __syncwarp();
    if (lane < 8) {
        float e[9]; float mx = -1e30f;
#pragma unroll
        for (int o = 0; o < 9; o++) { e[o] = sh[warp][o][lane]; mx = fmaxf(mx, e[o]); }
        float sm = 0.f;
#pragma unroll
        for (int o = 0; o < 9; o++) { e[o] = expf(e[o] - mx); sm += e[o]; }
        float inv = 1.f / sm;
#pragma unroll
        for (int o = 0; o < 9; o++) sh[warp][o][lane] = e[o] * inv;
    }
    __syncwarp();
    float acc[8] = {0.f, 0.f, 0.f, 0.f, 0.f, 0.f, 0.f, 0.f};
    for (int o = 0; o < 9; o++) {
        int ys = y + o / 3 - 1, xs = x + o % 3 - 1;
        if (ys < 0 || ys >= 64 || xs < 0 || xs >= 64) continue;
        const float* op = offs + (size_t)((b << 12) + (ys << 6) + xs) * 18 + 2 * o;
        float px = op[0], py = op[1];
        float y0f = floorf(py), x0f = floorf(px);
        float wy = py - y0f, wx = px - x0f;
        int y0 = (int)y0f, x0 = (int)x0f;
        float w00 = (1.f - wy) * (1.f - wx), w01 = (1.f - wy) * wx;
        float w10 = wy * (1.f - wx), w11 = wy * wx;
        bool vy0 = (y0 >= 0) && (y0 < 64), vy1 = (y0 + 1 >= 0) && (y0 + 1 < 64);
        bool vx0 = (x0 >= 0) && (x0 < 64), vx1 = (x0 + 1 >= 0) && (x0 + 1 < 64);
        w00 = (vy0 && vx0) ? w00 : 0.f; w01 = (vy0 && vx1) ? w01 : 0.f;
        w10 = (vy1 && vx0) ? w10 : 0.f; w11 = (vy1 && vx1) ? w11 : 0.f;
        int y0c = min(max(y0, 0), 63), y1c = min(max(y0 + 1, 0), 63);
        int x0c = min(max(x0, 0), 63), x1c = min(max(x0 + 1, 0), 63);
        float c00[8], c01[8], c10[8], c11[8];
        LOAD8H(c00, kvb + ((size_t)((y0c << 6) + x0c) << 9) + 256 + lane * 8);
        LOAD8H(c01, kvb + ((size_t)((y0c << 6) + x1c) << 9) + 256 + lane * 8);
        LOAD8H(c10, kvb + ((size_t)((y1c << 6) + x0c) << 9) + 256 + lane * 8);
        LOAD8H(c11, kvb + ((size_t)((y1c << 6) + x1c) << 9) + 256 + lane * 8);
#pragma unroll
        for (int h = 0; h < 8; h++) {
            float vv = w00 * c00[h] + w01 * c01[h] + w10 * c10[h] + w11 * c11[h];
            acc[h] += sh[warp][o][h] * vv;
        }
    }
    __half2 h0 = __floats2half2_rn(acc[0], acc[1]);
    __half2 h1 = __floats2half2_rn(acc[2], acc[3]);
    __half2 h2 = __floats2half2_rn(acc[4], acc[5]);
    __half2 h3 = __floats2half2_rn(acc[6], acc[7]);
    uint4 pk;
    pk.x = *reinterpret_cast<uint32_t*>(&h0);
    pk.y = *reinterpret_cast<uint32_t*>(&h1);
    pk.z = *reinterpret_cast<uint32_t*>(&h2);
    pk.w = *reinterpret_cast<uint32_t*>(&h3);
    *reinterpret_cast<uint4*>(outp + (size_t)p * 256 + lane * 8) = pk;
}

// ---------------- host ----------------
extern "C" void kernel_launch(void* const* d_in, const int* in_sizes, int n_in,
                              void* d_out, int out_size) {
    const float* x_q    = (const float*)d_in[0];
    const float* x_kv   = (const float*)d_in[1];
    const float* n1w    = (const float*)d_in[2];
    const float* n1b    = (const float*)d_in[3];
    const float* q_w    = (const float*)d_in[4];
    const float* q_b    = (const float*)d_in[5];
    const float* kv_w   = (const float*)d_in[6];
    const float* kv_b   = (const float*)d_in[7];
    const float* off1_w = (const float*)d_in[8];
    const float* off1_b = (const float*)d_in[9];
    const float* off2_w = (const float*)d_in[10];
    const float* off2_b = (const float*)d_in[11];
    const float* proj_w = (const float*)d_in[12];
    const float* proj_b = (const float*)d_in[13];
    const float* n2w    = (const float*)d_in[14];
    const float* n2b    = (const float*)d_in[15];
    const float* fc1_w  = (const float*)d_in[16];
    const float* fc1_b  = (const float*)d_in[17];
    const float* fc2_w  = (const float*)d_in[18];
    const float* fc2_b  = (const float*)d_in[19];
    float* out = (float*)d_out;

    __half *xall, *kvb, *att, *xn2, *hid, *wr, *wh;
    float *qb, *h1, *offs, *xres, *st1, *st2;
    float2* part;
    cudaGetSymbolAddress((void**)&xall, g_xall);
    cudaGetSymbolAddress((void**)&qb,   g_q);
    cudaGetSymbolAddress((void**)&kvb,  g_kv);
    cudaGetSymbolAddress((void**)&h1,   g_h1);
    cudaGetSymbolAddress((void**)&offs, g_offs);
    cudaGetSymbolAddress((void**)&att,  g_att);
    cudaGetSymbolAddress((void**)&xres, g_xres);
    cudaGetSymbolAddress((void**)&xn2,  g_xn2);
    cudaGetSymbolAddress((void**)&hid,  g_hid);
    cudaGetSymbolAddress((void**)&wr,   g_wr);
    cudaGetSymbolAddress((void**)&wh,   g_wh);
    cudaGetSymbolAddress((void**)&part, g_part);
    cudaGetSymbolAddress((void**)&st1,  g_st1);
    cudaGetSymbolAddress((void**)&st2,  g_st2);

    __half* qwh  = wh;
    __half* kvwh = qwh  + 65536;
    __half* pwh  = kvwh + 131072;
    __half* f1wh = pwh  + 65536;
    __half* f2wh = f1wh + 262144;

    cudaFuncSetAttribute(gemm_tc, cudaFuncAttributeMaxDynamicSharedMemorySize, SMEM_REQ);

    prep_k<<<7680, 256>>>(off1_w, wr, q_w, qwh, kv_w, kvwh, proj_w, pwh,
                          fc1_w, f1wh, fc2_w, f2wh);
    gn_p1<<<256, 256>>>(x_q, x_kv, part);
    gn_p2<<<1, 256>>>(part, st1, 8);
    norm_pack_k<<<dim3(128, 8, 8), dim3(32, 8)>>>(x_q, x_kv, st1, n1w, n1b, xall);

    GJob zero = {};
    // fused q + kv + conv (conv first)
    {
        GJob jc  = {xall,       wr,   off1_b, h1,          nullptr, 256, 4608, 512, 2, 1, 0.f};
        GJob jkv = {xall + 256, kvwh, kv_b,   (float*)kvb, nullptr, 512, 256,  512, 6, 0, 0.f};
        GJob jq  = {xall,       qwh,  q_b,    qb,          nullptr, 256, 256,  512, 1, 0,
                    0.17677669529663689f};
        gemm_tc<<<1024, 256, SMEM_REQ>>>(jc, jkv, jq, 256, 768);
    }
    off2_k<<<(MTOT * 18) / 256, 256>>>(h1, off2_w, off2_b, offs);
    attn_k<<<2048, 256>>>(qb, kvb, offs, att);
    // xres = x_q + att @ proj_w^T + b
    {
        GJob jp = {att, pwh, proj_b, xres, x_q, 256, 256, 256, 4, 0, 0.f};
        gemm_tc<<<256, 256, SMEM_REQ>>>(jp, zero, zero, 256, 256);
    }
    gn_p1<<<128, 256>>>(xres, xres, part);
    gn_p2<<<1, 256>>>(part, st2, 4);
    norm2_k<<<(MTOT * 256) / 256, 256>>>(xres, st2, n2w, n2b, xn2);
    // hid = gelu(xn2 @ fc1_w^T + b) -> half
    {
        GJob jf1 = {xn2, f1wh, fc1_b, (float*)hid, nullptr, 1024, 256, 256, 3, 0, 0.f};
        gemm_tc<<<1024, 256, SMEM_REQ>>>(jf1, zero, zero, 1024, 1024);
    }
    // out(NCHW) = xres + hid @ fc2_w^T + b   (256 CTAs: 128 M-blocks x 2 N-blocks)
    {
        GJob jf2 = {hid, f2wh, fc2_b, out, xres, 256, 1024, 1024, 5, 0, 0.f};
        gemm_tc<<<256, 256, SMEM_REQ>>>(jf2, zero, zero, 256, 256);
    }
}